// round 1
// baseline (speedup 1.0000x reference)
#include <cuda_runtime.h>

// ---------------- problem geometry (static per reference) ----------------
#define BB   2
#define CC   96
#define DD   32
#define HH   64
#define WW   64
#define D2   16
#define H2   32
#define W2   32
#define KDIM 768      // 8*C
#define NDIM 192      // 2*C

#define YSTR 33       // padded stride of transposed Y tile: YT[k][w'], 768 x 33
#define KT   64       // GEMM K tile

// Folded weights: W' = diag(gamma)*W, gW = gamma@W, bW = beta@W
__device__ float g_Wp[KDIM * NDIM];
__device__ float g_gW[NDIM];
__device__ float g_bW[NDIM];

// ---------------- prep: fold gamma/beta into the weight ----------------
__global__ void prep_kernel(const float* __restrict__ gamma,
                            const float* __restrict__ beta,
                            const float* __restrict__ w) {
    const int n   = blockIdx.x;      // one column per block
    const int tid = threadIdx.x;     // 128 threads
    float sg = 0.f, sb = 0.f;
    for (int k = tid; k < KDIM; k += 128) {
        float wv = w[k * NDIM + n];
        float g  = gamma[k];
        g_Wp[k * NDIM + n] = g * wv;
        sg += g * wv;
        sb += beta[k] * wv;
    }
    __shared__ float rs[8];
    #pragma unroll
    for (int o = 16; o > 0; o >>= 1) {
        sg += __shfl_down_sync(0xffffffffu, sg, o);
        sb += __shfl_down_sync(0xffffffffu, sb, o);
    }
    if ((tid & 31) == 0) { rs[tid >> 5] = sg; rs[4 + (tid >> 5)] = sb; }
    __syncthreads();
    if (tid == 0) {
        g_gW[n] = rs[0] + rs[1] + rs[2] + rs[3];
        g_bW[n] = rs[4] + rs[5] + rs[6] + rs[7];
    }
}

// ---------------- fused gather + LN-stats + GEMM + epilogue ----------------
// grid: 1024 blocks = (b, d', h'); block: 256 threads.
// Each block computes the 32 (w') x 192 (out-chan) tile for its (b,d',h').
__global__ __launch_bounds__(256, 1)
void pm_kernel(const float* __restrict__ x, float* __restrict__ out) {
    extern __shared__ float smem[];
    float* YT   = smem;                      // [KDIM][YSTR] = 25344 floats
    float* Wsm  = smem + KDIM * YSTR;        // [KT][NDIM]   = 12288 floats
    float* Csm  = Wsm;                       // reuse after GEMM: [NDIM][33] = 6336
    float* red  = Wsm + KT * NDIM;
    float* part_s  = red;                    // [8][32]
    float* part_s2 = red + 256;              // [8][32]
    float* mu_s    = red + 512;              // [32]
    float* rstd_s  = red + 544;              // [32]

    const int bid = blockIdx.x;
    const int h2  = bid & 31;
    const int d2  = (bid >> 5) & 15;
    const int b   = bid >> 9;

    const int tid = threadIdx.x;
    const int tw  = tid & 31;   // w' row handled in gather
    const int tc  = tid >> 5;   // channel stripe 0..7

    // ---- gather the 8 octant sub-lattices into smem (transposed) ----
    const float* xb = x + (size_t)b * (CC * DD * HH * WW)
                        + (size_t)(2 * d2) * (HH * WW)
                        + (2 * h2) * WW + 2 * tw;

    float s = 0.f, s2 = 0.f;
    #pragma unroll
    for (int oct = 0; oct < 8; oct++) {
        const int dd = (oct >> 2) & 1, hh = (oct >> 1) & 1, ww = oct & 1;
        const float* xo = xb + dd * (HH * WW) + hh * WW + ww;
        #pragma unroll
        for (int u = 0; u < 12; u++) {
            int c   = tc + 8 * u;
            float v = xo[(size_t)c * (DD * HH * WW)];
            YT[(oct * 96 + c) * YSTR + tw] = v;
            s  += v;
            s2 += v * v;
        }
    }
    part_s [tc * 32 + tw] = s;
    part_s2[tc * 32 + tw] = s2;
    __syncthreads();
    if (tid < 32) {
        float S = 0.f, S2 = 0.f;
        #pragma unroll
        for (int j = 0; j < 8; j++) { S += part_s[j * 32 + tid]; S2 += part_s2[j * 32 + tid]; }
        float mu  = S * (1.f / 768.f);
        float var = S2 * (1.f / 768.f) - mu * mu;
        mu_s[tid]   = mu;
        rstd_s[tid] = rsqrtf(var + 1e-5f);
    }

    // ---- GEMM: C[32 x 192] = Y[32 x 768] @ Wp[768 x 192] ----
    const int colg = tid & 31;   // base output column
    const int rowg = tid >> 5;   // 0..7
    const int r0   = rowg * 4;   // 4 rows per thread

    float acc[4][6];
    #pragma unroll
    for (int i = 0; i < 4; i++)
        #pragma unroll
        for (int j = 0; j < 6; j++) acc[i][j] = 0.f;

    for (int kt = 0; kt < KDIM; kt += KT) {
        __syncthreads();
        #pragma unroll
        for (int r = 0; r < (KT * NDIM) / 256; r++) {   // 48 coalesced loads/thread
            int idx = tid + 256 * r;
            Wsm[idx] = g_Wp[kt * NDIM + idx];
        }
        __syncthreads();
        #pragma unroll 4
        for (int kk = 0; kk < KT; kk++) {
            const float* yrow = &YT[(kt + kk) * YSTR + r0];
            float y0 = yrow[0], y1 = yrow[1], y2 = yrow[2], y3 = yrow[3];
            #pragma unroll
            for (int j = 0; j < 6; j++) {
                float w = Wsm[kk * NDIM + colg + 32 * j];
                acc[0][j] += y0 * w;
                acc[1][j] += y1 * w;
                acc[2][j] += y2 * w;
                acc[3][j] += y3 * w;
            }
        }
    }

    // ---- epilogue: fold LN affine, stage through smem, coalesced store ----
    __syncthreads();   // last W tile no longer needed; Csm reuses that space
    float mu0[4], rs0[4];
    #pragma unroll
    for (int i = 0; i < 4; i++) { mu0[i] = mu_s[r0 + i]; rs0[i] = rstd_s[r0 + i]; }
    #pragma unroll
    for (int j = 0; j < 6; j++) {
        int n = colg + 32 * j;
        float gw = g_gW[n], bw = g_bW[n];
        #pragma unroll
        for (int i = 0; i < 4; i++) {
            Csm[n * 33 + (r0 + i)] = rs0[i] * acc[i][j] + (bw - mu0[i] * rs0[i] * gw);
        }
    }
    __syncthreads();
    float* ob = out + (size_t)b * (NDIM * D2 * H2 * W2) + d2 * (H2 * W2) + h2 * W2;
    #pragma unroll
    for (int r = 0; r < (NDIM * 32) / 256; r++) {   // 24 coalesced stores/thread
        int idx = tid + 256 * r;
        int n = idx >> 5, w = idx & 31;
        ob[(size_t)n * (D2 * H2 * W2) + w] = Csm[n * 33 + w];
    }
}

// ---------------- launch ----------------
extern "C" void kernel_launch(void* const* d_in, const int* in_sizes, int n_in,
                              void* d_out, int out_size) {
    const float* x     = (const float*)d_in[0];
    const float* gamma = (const float*)d_in[1];
    const float* beta  = (const float*)d_in[2];
    const float* w     = (const float*)d_in[3];
    float* out = (float*)d_out;

    const int smem_bytes = (KDIM * YSTR + KT * NDIM + 576) * (int)sizeof(float); // 152832
    cudaFuncSetAttribute(pm_kernel, cudaFuncAttributeMaxDynamicSharedMemorySize, smem_bytes);

    prep_kernel<<<NDIM, 128>>>(gamma, beta, w);
    pm_kernel<<<BB * D2 * H2, 256, smem_bytes>>>(x, out);
}

// round 3
// speedup vs baseline: 2.3206x; 2.3206x over previous
#include <cuda_runtime.h>
#include <cuda_bf16.h>
#include <cstdint>

// ---------------- problem geometry (static) ----------------
#define CC   96
#define DDIM 32
#define HDIM 64
#define WDIM 64
#define HW   (HDIM*WDIM)         // 4096
#define DHW  (DDIM*HDIM*WDIM)    // 131072
#define CDHW (CC*DHW)
#define D2   16
#define H2   32
#define W2   32
#define OSP  (D2*H2*W2)          // 16384
#define KDIM 768
#define NDIM 192
#define KC   128
#define NCH  6                   // 768/128
#define NCTA 256                 // 32768 rows / 128

// ---------------- smem layout (bytes) ----------------
#define ASTR 272                 // 128 bf16 + 8 pad  (16B-aligned, conflict-free)
#define BSTR 272
#define SZ_A (128*ASTR)          // 34816
#define SZ_B (NDIM*BSTR)         // 52224
#define OFF_AH 0
#define OFF_AL SZ_A
#define OFF_BH (2*SZ_A)          // 69632
#define OFF_BL (2*SZ_A + SZ_B)   // 121856
#define OFF_MU   (2*SZ_A + 2*SZ_B)     // 174080
#define OFF_RSTD (OFF_MU + 512)
#define SMEM_TOTAL (OFF_MU + 1024)     // 175104
#define CSTR 132                 // epilogue staging stride (floats)

// ---------------- folded weights (bf16 hi/lo, [N][K] k-major) ----------------
__device__ __align__(16) __nv_bfloat16 g_Bhi[NDIM * KDIM];
__device__ __align__(16) __nv_bfloat16 g_Blo[NDIM * KDIM];
__device__ float g_bW[NDIM];

// ---------------- helpers ----------------
__device__ __forceinline__ uint32_t smem_u32(const void* p) {
    uint32_t a;
    asm("{ .reg .u64 t; cvta.to.shared.u64 t, %1; cvt.u32.u64 %0, t; }" : "=r"(a) : "l"(p));
    return a;
}
__device__ __forceinline__ void ldsm4(uint32_t* r, uint32_t addr) {
    asm volatile("ldmatrix.sync.aligned.m8n8.x4.shared.b16 {%0,%1,%2,%3}, [%4];"
                 : "=r"(r[0]), "=r"(r[1]), "=r"(r[2]), "=r"(r[3]) : "r"(addr));
}
__device__ __forceinline__ void mma_bf16(float* c, const uint32_t* a, uint32_t b0, uint32_t b1) {
    asm volatile("mma.sync.aligned.m16n8k16.row.col.f32.bf16.bf16.f32 "
                 "{%0,%1,%2,%3}, {%4,%5,%6,%7}, {%8,%9}, {%0,%1,%2,%3};"
                 : "+f"(c[0]), "+f"(c[1]), "+f"(c[2]), "+f"(c[3])
                 : "r"(a[0]), "r"(a[1]), "r"(a[2]), "r"(a[3]), "r"(b0), "r"(b1));
}
__device__ __forceinline__ int octoff(int oct) {
    return ((oct >> 2) & 1) * HW + ((oct >> 1) & 1) * WDIM + (oct & 1);
}

// ---------------- prep: fold gamma into W, split bf16 hi/lo, bias vector ----------------
__global__ void prep_kernel(const float* __restrict__ gamma,
                            const float* __restrict__ beta,
                            const float* __restrict__ w) {
    const int n = blockIdx.x;
    const int tid = threadIdx.x;   // 128
    float sb = 0.f;
    for (int k = tid; k < KDIM; k += 128) {
        float wv = w[k * NDIM + n];
        float wp = gamma[k] * wv;
        __nv_bfloat16 hi = __float2bfloat16_rn(wp);
        g_Bhi[n * KDIM + k] = hi;
        g_Blo[n * KDIM + k] = __float2bfloat16_rn(wp - __bfloat162float(hi));
        sb += beta[k] * wv;
    }
    __shared__ float rs[4];
    #pragma unroll
    for (int o = 16; o > 0; o >>= 1) sb += __shfl_down_sync(0xffffffffu, sb, o);
    if ((tid & 31) == 0) rs[tid >> 5] = sb;
    __syncthreads();
    if (tid == 0) g_bW[n] = rs[0] + rs[1] + rs[2] + rs[3];
}

// ---------------- fused gather + LN + warp-mma GEMM ----------------
// grid 256 CTAs x 256 threads; CTA computes rows [bid*128, +128) x 192 cols.
__global__ __launch_bounds__(256, 1)
void pm_kernel(const float* __restrict__ x, float* __restrict__ out) {
    extern __shared__ char smem[];
    const uint32_t sbase = smem_u32(smem);
    const int tid  = threadIdx.x;
    const int bid  = blockIdx.x;
    const int lane = tid & 31;
    const int wid  = tid >> 5;
    const int r    = tid & 127;   // A row this thread fills
    const int q    = tid >> 7;    // K half (0/1) within chunk

    // per-thread gmem row base
    const int grp = bid * 4 + (r >> 5);
    const int h2i = grp & 31, d2i = (grp >> 5) & 15, bi = grp >> 9;
    const float* xr = x + (size_t)bi * CDHW + (2 * d2i) * HW + (2 * h2i) * WDIM + 2 * (r & 31);

    // ---- phase 1: mean / rstd per row ----
    float* ps = (float*)smem;
    float s = 0.f, s2 = 0.f;
    #pragma unroll 1
    for (int ch = 0; ch < NCH; ch++) {
        int k0 = ch * KC + q * 64;
        int oct = k0 / 96, c = k0 - oct * 96;
        int ob = octoff(oct);
        #pragma unroll
        for (int p = 0; p < 32; p++) {
            float v0 = __ldg(xr + ob + (size_t)c * DHW);
            float v1 = __ldg(xr + ob + (size_t)(c + 1) * DHW);
            s += v0 + v1; s2 += v0 * v0 + v1 * v1;
            c += 2;
            if (c == 96) { c = 0; oct++; ob = octoff(oct); }
        }
    }
    ps[tid] = s; ps[256 + tid] = s2;
    __syncthreads();
    float* mu_s   = (float*)(smem + OFF_MU);
    float* rstd_s = (float*)(smem + OFF_RSTD);
    if (tid < 128) {
        float S  = ps[tid] + ps[tid + 128];
        float S2 = ps[256 + tid] + ps[256 + tid + 128];
        float mu = S * (1.f / 768.f);
        float var = S2 * (1.f / 768.f) - mu * mu;
        mu_s[tid]   = mu;
        rstd_s[tid] = rsqrtf(var + 1e-5f);
    }
    __syncthreads();
    const float mu   = mu_s[r];
    const float rstd = rstd_s[r];

    // ---- mma thread/warp geometry ----
    const int wm = wid >> 2;   // 0..1 -> 64 rows
    const int wn = wid & 3;    // 0..3 -> 48 cols
    const uint32_t aAh = sbase + OFF_AH + (uint32_t)(wm * 64 + (lane & 15)) * ASTR + (lane >> 4) * 16;
    const uint32_t aAl = aAh + SZ_A;
    const uint32_t aBh = sbase + OFF_BH
                       + (uint32_t)(wn * 48 + (lane & 7) + ((lane >> 4) << 3)) * BSTR
                       + ((lane >> 3) & 1) * 16;
    const uint32_t aBl = aBh + SZ_B;

    float acc[4][6][4];
    #pragma unroll
    for (int mt = 0; mt < 4; mt++)
        #pragma unroll
        for (int nt = 0; nt < 6; nt++)
            #pragma unroll
            for (int e = 0; e < 4; e++) acc[mt][nt][e] = 0.f;

    const uint4* bh4 = (const uint4*)g_Bhi;
    const uint4* bl4 = (const uint4*)g_Blo;
    char* aDst = smem + (uint32_t)r * ASTR + q * 128;

    // ---- main loop over K chunks ----
    #pragma unroll 1
    for (int ch = 0; ch < NCH; ch++) {
        const int kt = ch * KC;
        __syncthreads();   // previous chunk's mma done before overwrite

        // fill A (z = (x-mu)*rstd, bf16 hi/lo)
        {
            int k0 = kt + q * 64;
            int oct = k0 / 96, c = k0 - oct * 96;
            int ob = octoff(oct);
            uint32_t hb[4], lb[4];
            #pragma unroll
            for (int p = 0; p < 32; p++) {
                float v0 = __ldg(xr + ob + (size_t)c * DHW);
                float v1 = __ldg(xr + ob + (size_t)(c + 1) * DHW);
                float z0 = (v0 - mu) * rstd;
                float z1 = (v1 - mu) * rstd;
                __nv_bfloat16 h0 = __float2bfloat16_rn(z0);
                __nv_bfloat16 h1 = __float2bfloat16_rn(z1);
                __nv_bfloat16 l0 = __float2bfloat16_rn(z0 - __bfloat162float(h0));
                __nv_bfloat16 l1 = __float2bfloat16_rn(z1 - __bfloat162float(h1));
                hb[p & 3] = (uint32_t)__bfloat16_as_ushort(h0) | ((uint32_t)__bfloat16_as_ushort(h1) << 16);
                lb[p & 3] = (uint32_t)__bfloat16_as_ushort(l0) | ((uint32_t)__bfloat16_as_ushort(l1) << 16);
                if ((p & 3) == 3) {
                    *(uint4*)(aDst + (p >> 2) * 16)        = make_uint4(hb[0], hb[1], hb[2], hb[3]);
                    *(uint4*)(aDst + SZ_A + (p >> 2) * 16) = make_uint4(lb[0], lb[1], lb[2], lb[3]);
                }
                c += 2;
                if (c == 96) { c = 0; oct++; ob = octoff(oct); }
            }
        }
        // fill B (bf16 hi/lo from gmem, coalesced 16B)
        #pragma unroll
        for (int i = 0; i < 12; i++) {
            int idx = tid + 256 * i;
            int n = idx >> 4, j = idx & 15;
            uint4 vh = __ldg(&bh4[n * 96 + (kt >> 3) + j]);
            uint4 vl = __ldg(&bl4[n * 96 + (kt >> 3) + j]);
            *(uint4*)(smem + OFF_BH + n * BSTR + j * 16) = vh;
            *(uint4*)(smem + OFF_BL + n * BSTR + j * 16) = vl;
        }
        __syncthreads();

        // mma over 8 k-steps, 3 split terms
        #pragma unroll
        for (int ks = 0; ks < 8; ks++) {
            uint32_t af[4][4], al[4][4], bf[3][4];
            #pragma unroll
            for (int mt = 0; mt < 4; mt++) ldsm4(af[mt], aAh + mt * (16 * ASTR) + ks * 32);
            #pragma unroll
            for (int np = 0; np < 3; np++) ldsm4(bf[np], aBh + np * (16 * BSTR) + ks * 32);
            #pragma unroll
            for (int mt = 0; mt < 4; mt++)
                #pragma unroll
                for (int nt = 0; nt < 6; nt++)
                    mma_bf16(acc[mt][nt], af[mt], bf[nt >> 1][(nt & 1) * 2], bf[nt >> 1][(nt & 1) * 2 + 1]);
            #pragma unroll
            for (int mt = 0; mt < 4; mt++) ldsm4(al[mt], aAl + mt * (16 * ASTR) + ks * 32);
            #pragma unroll
            for (int mt = 0; mt < 4; mt++)
                #pragma unroll
                for (int nt = 0; nt < 6; nt++)
                    mma_bf16(acc[mt][nt], al[mt], bf[nt >> 1][(nt & 1) * 2], bf[nt >> 1][(nt & 1) * 2 + 1]);
            #pragma unroll
            for (int np = 0; np < 3; np++) ldsm4(bf[np], aBl + np * (16 * BSTR) + ks * 32);
            #pragma unroll
            for (int mt = 0; mt < 4; mt++)
                #pragma unroll
                for (int nt = 0; nt < 6; nt++)
                    mma_bf16(acc[mt][nt], af[mt], bf[nt >> 1][(nt & 1) * 2], bf[nt >> 1][(nt & 1) * 2 + 1]);
        }
    }

    // ---- epilogue: stage C in smem (transposed), coalesced store + bias ----
    __syncthreads();
    float* Csm = (float*)smem;
    #pragma unroll
    for (int mt = 0; mt < 4; mt++) {
        int row = wm * 64 + mt * 16 + (lane >> 2);
        #pragma unroll
        for (int nt = 0; nt < 6; nt++) {
            int n = wn * 48 + nt * 8 + 2 * (lane & 3);
            Csm[n * CSTR + row]           = acc[mt][nt][0];
            Csm[(n + 1) * CSTR + row]     = acc[mt][nt][1];
            Csm[n * CSTR + row + 8]       = acc[mt][nt][2];
            Csm[(n + 1) * CSTR + row + 8] = acc[mt][nt][3];
        }
    }
    __syncthreads();
    #pragma unroll 8
    for (int i = 0; i < 96; i++) {
        int idx = tid + 256 * i;
        int n = idx >> 7, row = idx & 127;
        int grp2 = bid * 4 + (row >> 5);
        int h2o = grp2 & 31, d2o = (grp2 >> 5) & 15, bo = grp2 >> 9;
        out[(size_t)bo * NDIM * OSP + (size_t)n * OSP + d2o * (H2 * W2) + h2o * W2 + (row & 31)]
            = Csm[n * CSTR + row] + g_bW[n];
    }
}

// ---------------- launch ----------------
extern "C" void kernel_launch(void* const* d_in, const int* in_sizes, int n_in,
                              void* d_out, int out_size) {
    const float* x     = (const float*)d_in[0];
    const float* gamma = (const float*)d_in[1];
    const float* beta  = (const float*)d_in[2];
    const float* w     = (const float*)d_in[3];
    float* out = (float*)d_out;

    cudaFuncSetAttribute(pm_kernel, cudaFuncAttributeMaxDynamicSharedMemorySize, SMEM_TOTAL);

    prep_kernel<<<NDIM, 128>>>(gamma, beta, w);
    pm_kernel<<<NCTA, 256, SMEM_TOTAL>>>(x, out);
}

// round 4
// speedup vs baseline: 2.8069x; 1.2095x over previous
#include <cuda_runtime.h>
#include <cuda_bf16.h>
#include <cstdint>

// ---------------- problem geometry (static) ----------------
#define CC   96
#define DDIM 32
#define HDIM 64
#define WDIM 64
#define HW   4096
#define DHW  131072
#define CDHW (CC*DHW)
#define D2   16
#define H2   32
#define W2   32
#define OSP  16384
#define KDIM 768
#define NDIM 192
#define NCHK 4                   // K chunks of 192 (one octant-pair each)
#define NCTA 256

// ---------------- smem layout (bytes) ----------------
#define ASTR 400                 // 192 bf16 + 8 pad ; 400/16=25 (odd) -> ldmatrix conflict-free
#define SZ_AH (128*ASTR)         // 51200
#define BUFSZ (2*SZ_AH)          // hi+lo = 102400
#define OFF_PS   (2*BUFSZ)       // 204800 : ps[256]+ps2[256]
#define OFF_RSTD (OFF_PS+2048)   // 206848 : rstd[128]
#define OFF_MRS  (OFF_RSTD+512)  // 207360 : mu*rstd[128]
#define SMEM_TOTAL (OFF_MRS+512) // 207872
#define CSTR 132                 // epilogue staging stride (floats)

// ---------------- prep outputs ----------------
// B fragments: [kt 0..47][ntile 0..23][lane 0..31] = {bh0,bh1,bl0,bl1}
__device__ __align__(16) uint4 g_Bf[48*24*32];
__device__ float g_gW[NDIM];     // gamma @ W
__device__ float g_bW[NDIM];     // beta  @ W

// ---------------- helpers ----------------
__device__ __forceinline__ uint32_t smem_u32(const void* p) {
    uint32_t a;
    asm("{ .reg .u64 t; cvta.to.shared.u64 t, %1; cvt.u32.u64 %0, t; }" : "=r"(a) : "l"(p));
    return a;
}
__device__ __forceinline__ void ldsm4(uint32_t* r, uint32_t addr) {
    asm volatile("ldmatrix.sync.aligned.m8n8.x4.shared.b16 {%0,%1,%2,%3}, [%4];"
                 : "=r"(r[0]), "=r"(r[1]), "=r"(r[2]), "=r"(r[3]) : "r"(addr));
}
__device__ __forceinline__ void mma_bf16(float* c, const uint32_t* a, uint32_t b0, uint32_t b1) {
    asm volatile("mma.sync.aligned.m16n8k16.row.col.f32.bf16.bf16.f32 "
                 "{%0,%1,%2,%3}, {%4,%5,%6,%7}, {%8,%9}, {%0,%1,%2,%3};"
                 : "+f"(c[0]), "+f"(c[1]), "+f"(c[2]), "+f"(c[3])
                 : "r"(a[0]), "r"(a[1]), "r"(a[2]), "r"(a[3]), "r"(b0), "r"(b1));
}
// split (a,b) -> packed bf16 hi pair + lo pair (low half = first arg = even k)
__device__ __forceinline__ void split2(float a, float b, uint32_t& hi, uint32_t& lo) {
    __nv_bfloat162 h = __floats2bfloat162_rn(a, b);
    uint32_t hu = *(uint32_t*)&h;
    float ha = __uint_as_float(hu << 16);
    float hb = __uint_as_float(hu & 0xffff0000u);
    __nv_bfloat162 l = __floats2bfloat162_rn(a - ha, b - hb);
    hi = hu; lo = *(uint32_t*)&l;
}

__device__ __forceinline__ void split_val(float wv, __nv_bfloat16& h, float& rem) {
    h = __float2bfloat16_rn(wv);
    rem = wv - __bfloat162float(h);
}

// ---------------- prep 1: gW / bW vectors ----------------
__global__ void prep_vec(const float* __restrict__ gamma,
                         const float* __restrict__ beta,
                         const float* __restrict__ w) {
    const int n = blockIdx.x;
    const int tid = threadIdx.x;   // 128
    float sb = 0.f, sg = 0.f;
    for (int k = tid; k < KDIM; k += 128) {
        float wv = w[k * NDIM + n];
        sb += beta[k]  * wv;
        sg += gamma[k] * wv;
    }
    __shared__ float rs[8];
    #pragma unroll
    for (int o = 16; o > 0; o >>= 1) {
        sb += __shfl_down_sync(0xffffffffu, sb, o);
        sg += __shfl_down_sync(0xffffffffu, sg, o);
    }
    if ((tid & 31) == 0) { rs[tid >> 5] = sb; rs[4 + (tid >> 5)] = sg; }
    __syncthreads();
    if (tid == 0) {
        g_bW[n] = rs[0] + rs[1] + rs[2] + rs[3];
        g_gW[n] = rs[4] + rs[5] + rs[6] + rs[7];
    }
}

// ---------------- prep 2: B mma-fragments (hi/lo), W' = diag(gamma)*W ----------------
__global__ void prep_frag(const float* __restrict__ gamma,
                          const float* __restrict__ w) {
    const int idx = blockIdx.x * 128 + threadIdx.x;   // 0..36863
    const int kt   = idx / 768;
    const int rem  = idx - kt * 768;
    const int nt   = rem >> 5;
    const int lane = rem & 31;
    const int n  = nt * 8 + (lane >> 2);
    const int k0 = kt * 16 + (lane & 3) * 2;

    float w00 = gamma[k0]     * w[(k0)     * NDIM + n];
    float w01 = gamma[k0 + 1] * w[(k0 + 1) * NDIM + n];
    float w10 = gamma[k0 + 8] * w[(k0 + 8) * NDIM + n];
    float w11 = gamma[k0 + 9] * w[(k0 + 9) * NDIM + n];

    uint32_t bh0, bl0, bh1, bl1;
    split2(w00, w01, bh0, bl0);
    split2(w10, w11, bh1, bl1);
    g_Bf[idx] = make_uint4(bh0, bh1, bl0, bl1);
}

// ---------------- fused single-pass gather + raw-GEMM + LN-affine epilogue ----------------
// grid 256 CTAs x 256 threads; CTA computes rows [bid*128,+128) x 192 cols.
__global__ __launch_bounds__(256, 1)
void pm_kernel(const float* __restrict__ x, float* __restrict__ out) {
    extern __shared__ char smem[];
    const uint32_t sbase = smem_u32(smem);
    const int tid  = threadIdx.x;
    const int bid  = blockIdx.x;
    const int lane = tid & 31;
    const int wid  = tid >> 5;
    const int r    = tid & 127;   // A row this thread fills
    const int q    = tid >> 7;    // c-half within chunk

    const int grp = bid * 4 + (r >> 5);
    const int h2i = grp & 31, d2i = (grp >> 5) & 15, bi = grp >> 9;
    const float* xr = x + (size_t)bi * CDHW + (2 * d2i) * HW + (2 * h2i) * WDIM + 2 * (r & 31);

    // mma geometry: 2(m) x 4(n) warps; warp tile 64 x 48
    const int wm = wid >> 2;
    const int wn = wid & 3;
    const uint32_t aoff = (uint32_t)(wm * 64 + (lane & 15)) * ASTR + (lane >> 4) * 16;

    float acc[4][6][4];
    #pragma unroll
    for (int mt = 0; mt < 4; mt++)
        #pragma unroll
        for (int nt = 0; nt < 6; nt++)
            #pragma unroll
            for (int e = 0; e < 4; e++) acc[mt][nt][e] = 0.f;

    float s = 0.f, s2 = 0.f;

    // ---- fill chunk ch (octant pair) : raw y -> bf16 hi/lo in smem + stats ----
    auto fill = [&](int ch) {
        char* dst = smem + (ch & 1) * BUFSZ + (uint32_t)r * ASTR;
        const float* xc = xr + (ch >> 1) * HW + (ch & 1) * WDIM;
        int c = q * 48;
        #pragma unroll
        for (int t = 0; t < 24; t++, c += 2) {
            float2 va = *(const float2*)(xc + (size_t)c * DHW);        // k = c   (w=0), c over pair
            float2 vb = *(const float2*)(xc + (size_t)(c + 1) * DHW);  // k = c+1
            s  += (va.x + va.y) + (vb.x + vb.y);
            s2 += va.x * va.x + va.y * va.y + vb.x * vb.x + vb.y * vb.y;
            uint32_t h0, l0, h1, l1;
            split2(va.x, vb.x, h0, l0);   // kl = c, c+1   (w=0 octant)
            split2(va.y, vb.y, h1, l1);   // kl = 96+c,+1  (w=1 octant)
            *(uint32_t*)(dst + 2 * c)               = h0;
            *(uint32_t*)(dst + 192 + 2 * c)         = h1;
            *(uint32_t*)(dst + SZ_AH + 2 * c)       = l0;
            *(uint32_t*)(dst + SZ_AH + 192 + 2 * c) = l1;
        }
    };

    // ---- mma over one chunk (12 k-steps, 3 split terms, B via LDG fragments) ----
    auto mmachunk = [&](int ch) {
        const uint32_t abase = sbase + (ch & 1) * BUFSZ;
        const uint4* bp = g_Bf + ((size_t)(ch * 12) * 24 + wn * 6) * 32 + lane;
        uint32_t bb[2][6][4];
        #pragma unroll
        for (int nt = 0; nt < 6; nt++) {
            uint4 v = __ldg(bp + nt * 32);
            bb[0][nt][0] = v.x; bb[0][nt][1] = v.y; bb[0][nt][2] = v.z; bb[0][nt][3] = v.w;
        }
        #pragma unroll
        for (int ks = 0; ks < 12; ks++) {
            if (ks < 11) {
                const uint4* bp2 = bp + (size_t)(ks + 1) * 24 * 32;
                #pragma unroll
                for (int nt = 0; nt < 6; nt++) {
                    uint4 v = __ldg(bp2 + nt * 32);
                    bb[(ks + 1) & 1][nt][0] = v.x; bb[(ks + 1) & 1][nt][1] = v.y;
                    bb[(ks + 1) & 1][nt][2] = v.z; bb[(ks + 1) & 1][nt][3] = v.w;
                }
            }
            uint32_t af[4][4], al[4][4];
            #pragma unroll
            for (int mt = 0; mt < 4; mt++)
                ldsm4(af[mt], abase + aoff + mt * (16 * ASTR) + ks * 32);
            #pragma unroll
            for (int mt = 0; mt < 4; mt++)
                ldsm4(al[mt], abase + SZ_AH + aoff + mt * (16 * ASTR) + ks * 32);
            uint32_t (*B)[4] = bb[ks & 1];
            #pragma unroll
            for (int mt = 0; mt < 4; mt++)
                #pragma unroll
                for (int nt = 0; nt < 6; nt++)
                    mma_bf16(acc[mt][nt], af[mt], B[nt][0], B[nt][1]);
            #pragma unroll
            for (int mt = 0; mt < 4; mt++)
                #pragma unroll
                for (int nt = 0; nt < 6; nt++)
                    mma_bf16(acc[mt][nt], al[mt], B[nt][0], B[nt][1]);
            #pragma unroll
            for (int mt = 0; mt < 4; mt++)
                #pragma unroll
                for (int nt = 0; nt < 6; nt++)
                    mma_bf16(acc[mt][nt], af[mt], B[nt][2], B[nt][3]);
        }
    };

    fill(0);
    __syncthreads();
    #pragma unroll 1
    for (int ch = 0; ch < NCHK; ch++) {
        if (ch < NCHK - 1) fill(ch + 1);
        mmachunk(ch);
        __syncthreads();
    }

    // ---- LN stats reduction ----
    float* ps = (float*)(smem + OFF_PS);
    ps[tid] = s; ps[256 + tid] = s2;
    __syncthreads();
    float* rstd_s = (float*)(smem + OFF_RSTD);
    float* mrs_s  = (float*)(smem + OFF_MRS);
    if (tid < 128) {
        float S  = ps[tid] + ps[tid + 128];
        float S2 = ps[256 + tid] + ps[256 + tid + 128];
        float mu  = S * (1.f / 768.f);
        float var = S2 * (1.f / 768.f) - mu * mu;
        float rstd = rsqrtf(var + 1e-5f);
        rstd_s[tid] = rstd;
        mrs_s[tid]  = mu * rstd;
    }
    __syncthreads();

    // ---- epilogue: stage C transposed in smem (buf0 region), coalesced affine store ----
    float* Csm = (float*)smem;
    #pragma unroll
    for (int mt = 0; mt < 4; mt++) {
        int row = wm * 64 + mt * 16 + (lane >> 2);
        #pragma unroll
        for (int nt = 0; nt < 6; nt++) {
            int n = wn * 48 + nt * 8 + 2 * (lane & 3);
            Csm[n * CSTR + row]           = acc[mt][nt][0];
            Csm[(n + 1) * CSTR + row]     = acc[mt][nt][1];
            Csm[n * CSTR + row + 8]       = acc[mt][nt][2];
            Csm[(n + 1) * CSTR + row + 8] = acc[mt][nt][3];
        }
    }
    __syncthreads();
    #pragma unroll 8
    for (int i = 0; i < 96; i++) {
        int idx = tid + 256 * i;
        int n = idx >> 7, row = idx & 127;
        float val = rstd_s[row] * Csm[n * CSTR + row] - mrs_s[row] * g_gW[n] + g_bW[n];
        int grp2 = bid * 4 + (row >> 5);
        int h2o = grp2 & 31, d2o = (grp2 >> 5) & 15, bo = grp2 >> 9;
        out[(size_t)bo * NDIM * OSP + (size_t)n * OSP + d2o * (H2 * W2) + h2o * W2 + (row & 31)] = val;
    }
}

// ---------------- launch ----------------
extern "C" void kernel_launch(void* const* d_in, const int* in_sizes, int n_in,
                              void* d_out, int out_size) {
    const float* x     = (const float*)d_in[0];
    const float* gamma = (const float*)d_in[1];
    const float* beta  = (const float*)d_in[2];
    const float* w     = (const float*)d_in[3];
    float* out = (float*)d_out;

    cudaFuncSetAttribute(pm_kernel, cudaFuncAttributeMaxDynamicSharedMemorySize, SMEM_TOTAL);

    prep_vec<<<NDIM, 128>>>(gamma, beta, w);
    prep_frag<<<288, 128>>>(gamma, w);
    pm_kernel<<<NCTA, 256, SMEM_TOTAL>>>(x, out);
}